// round 2
// baseline (speedup 1.0000x reference)
#include <cuda_runtime.h>

#define Bn 64
#define H  384
#define HH (H*H)
#define BORDER 3
#define CROP 378
#define NSH 49

// corr tiling
#define TX 128
#define TY 16
#define GX 3    // ceil(378/128)
#define GY 24   // ceil(378/16)
#define NTILE (GX*GY)   // 72
#define HALO_W 136      // need 134, pad to 136 (16B-safe rows: 136*4=544)
#define HALO_H 22       // TY + 6

typedef unsigned long long ull;

// scratch (static device memory; no allocations anywhere)
__device__ float g_part[Bn*NTILE*NSH*3];  // per-tile partials: hp, pp, mp
__device__ float g_rows[Bn*H*21];         // per-row window sums (3 fields x 7 j)
__device__ float g_rowp[Bn*H];            // per-row pred sums
__device__ float g_bmin[Bn];              // per-batch min cMSE

// ---- f32x2 helpers -------------------------------------------------------
__device__ __forceinline__ ull pk2(float a, float b) {
    ull r; asm("mov.b64 %0, {%1,%2};" : "=l"(r) : "f"(a), "f"(b)); return r;
}
__device__ __forceinline__ void fma2(ull& acc, ull a, ull b) {
    asm("fma.rn.f32x2 %0, %1, %2, %0;" : "+l"(acc) : "l"(a), "l"(b));
}
__device__ __forceinline__ ull mul2(ull a, ull b) {
    ull r; asm("mul.rn.f32x2 %0, %1, %2;" : "=l"(r) : "l"(a), "l"(b)); return r;
}
__device__ __forceinline__ float ulo(ull u){ return __uint_as_float((unsigned)u); }
__device__ __forceinline__ float uhi(ull u){ return __uint_as_float((unsigned)(u>>32)); }

// ---------------------------------------------------------------------------
// box_kernel v2: per-row window sums for fields {m, m*h, m*h^2} (7 j-offsets)
// plus per-row pred sums. grid (48, Bn), 128 threads, 8 rows per block.
// ---------------------------------------------------------------------------
__global__ __launch_bounds__(128) void box_kernel(
    const float* __restrict__ sr, const float* __restrict__ hr,
    const float* __restrict__ mk)
{
    const int batch = blockIdx.y;
    const float* mb = mk + (size_t)batch*HH;
    const float* hb = hr + (size_t)batch*HH;
    const float* sb = sr + (size_t)batch*HH;

    const int tid  = threadIdx.x;
    const int w    = tid >> 5;
    const int lane = tid & 31;

    #pragma unroll
    for (int ry = 0; ry < 2; ry++) {
        const int y = blockIdx.x*8 + w*2 + ry;
        float tm = 0.f, tmh = 0.f, tmh2 = 0.f, tp = 0.f;
        float fm[6], fmh[6], fmh2[6];   // x = 0..5
        float bm[6], bmh[6], bmh2[6];   // x = 378..383
        #pragma unroll
        for (int c = 0; c < 12; c++) {
            const int x = c*32 + lane;
            const float m  = mb[y*H + x];
            const float h  = hb[y*H + x];
            const float mh = m*h;
            const float mh2 = mh*h;
            tm += m; tmh += mh; tmh2 += mh2;
            if (x >= BORDER && x < H-BORDER && y >= BORDER && y < H-BORDER)
                tp += sb[y*H + x] * m;
            if (c == 0) {
                #pragma unroll
                for (int j = 0; j < 6; j++) {
                    fm[j]   = __shfl_sync(0xffffffffu, m,   j);
                    fmh[j]  = __shfl_sync(0xffffffffu, mh,  j);
                    fmh2[j] = __shfl_sync(0xffffffffu, mh2, j);
                }
            }
            if (c == 11) {
                #pragma unroll
                for (int j = 0; j < 6; j++) {
                    bm[j]   = __shfl_sync(0xffffffffu, m,   26+j);
                    bmh[j]  = __shfl_sync(0xffffffffu, mh,  26+j);
                    bmh2[j] = __shfl_sync(0xffffffffu, mh2, 26+j);
                }
            }
        }
        #pragma unroll
        for (int off = 16; off; off >>= 1) {
            tm   += __shfl_xor_sync(0xffffffffu, tm,   off);
            tmh  += __shfl_xor_sync(0xffffffffu, tmh,  off);
            tmh2 += __shfl_xor_sync(0xffffffffu, tmh2, off);
            tp   += __shfl_xor_sync(0xffffffffu, tp,   off);
        }
        if (lane == 0) {
            float* out = g_rows + ((size_t)batch*H + y)*21;
            #pragma unroll
            for (int j = 0; j < 7; j++) {
                float lm = 0.f, lmh = 0.f, lmh2 = 0.f;
                float rm = 0.f, rmh = 0.f, rmh2 = 0.f;
                #pragma unroll
                for (int k = 0; k < 6; k++) {
                    if (k < j)  { lm += fm[k]; lmh += fmh[k]; lmh2 += fmh2[k]; }
                    if (k >= j) { rm += bm[k]; rmh += bmh[k]; rmh2 += bmh2[k]; }
                }
                out[0*7 + j] = tm   - lm   - rm;
                out[1*7 + j] = tmh  - lmh  - rmh;
                out[2*7 + j] = tmh2 - lmh2 - rmh2;
            }
            g_rowp[(size_t)batch*H + y] = tp;
        }
    }
}

// ---------------------------------------------------------------------------
// corr_kernel: three 7x7 correlations Shp, Spp, Smp via packed f32x2 FMA.
// 7 warps per block; warp w owns shift-row i = w.
// ---------------------------------------------------------------------------
__global__ __launch_bounds__(224, 2) void corr_kernel(
    const float* __restrict__ sr, const float* __restrict__ hr,
    const float* __restrict__ mk)
{
    __shared__ __align__(16) float s_m [HALO_H*HALO_W];
    __shared__ __align__(16) float s_mh[HALO_H*HALO_W];
    __shared__ __align__(16) float s_p [TY*TX];

    const int batch = blockIdx.z;
    const int x0 = blockIdx.x * TX;
    const int y0 = blockIdx.y * TY;
    const float* mb = mk + (size_t)batch*HH;
    const float* hb = hr + (size_t)batch*HH;
    const float* sb = sr + (size_t)batch*HH;
    const int tid = threadIdx.x;

    // halo tile of m and m*h (zero-fill OOB / pad columns)
    for (int idx = tid; idx < HALO_H*HALO_W; idx += 224) {
        const int r = idx / HALO_W, c = idx % HALO_W;
        const int y = y0 + r, x = x0 + c;
        float m = 0.f, mh = 0.f;
        if (c < 134 && y < H && x < H) {
            m  = mb[y*H + x];
            mh = m * hb[y*H + x];
        }
        s_m[idx] = m; s_mh[idx] = mh;
    }
    // pred tile (p = 0 outside valid crop)
    for (int idx = tid; idx < TY*TX; idx += 224) {
        const int r = idx / TX, c = idx % TX;
        const int y = y0 + r, x = x0 + c;
        float p = 0.f;
        if (y < CROP && x < CROP)
            p = sb[(y+BORDER)*H + x+BORDER] * mb[(y+BORDER)*H + x+BORDER];
        s_p[idx] = p;
    }
    __syncthreads();

    const int wid  = tid >> 5;      // shift row i = wid (0..6)
    const int lane = tid & 31;
    const int cb   = lane * 4;      // lane owns 4 consecutive output columns

    // sums: 0 = hp, 1 = mp, 2 = pp
    ull   accE[3][4];   // even j (0,2,4,6), fully packed over k
    ull   accM[3][3];   // odd j (1,3,5), middle k-pair packed
    float accS[3][3];   // odd j, edge k terms
    #pragma unroll
    for (int s = 0; s < 3; s++) {
        #pragma unroll
        for (int t = 0; t < 4; t++) accE[s][t] = 0ull;
        #pragma unroll
        for (int t = 0; t < 3; t++) { accM[s][t] = 0ull; accS[s][t] = 0.f; }
    }

    #pragma unroll 2
    for (int r = 0; r < TY; r++) {
        const ull* pvp = (const ull*)&s_p[r*TX + cb];
        const ull pv01 = pvp[0], pv23 = pvp[1];
        const ull qv01 = mul2(pv01, pv01), qv23 = mul2(pv23, pv23);
        const float pv0 = ulo(pv01), pv1 = uhi(pv01), pv2 = ulo(pv23), pv3 = uhi(pv23);
        const float qv0 = ulo(qv01), qv1 = uhi(qv01), qv2 = ulo(qv23), qv3 = uhi(qv23);
        const ull P12 = pk2(pv1, pv2);
        const ull Q12 = pk2(qv1, qv2);

        const int base = (r + wid)*HALO_W + cb;
        const ull* mp_ = (const ull*)&s_m [base];
        const ull* hp_ = (const ull*)&s_mh[base];
        ull mwp[5], hwp[5];
        #pragma unroll
        for (int t = 0; t < 5; t++) { mwp[t] = mp_[t]; hwp[t] = hp_[t]; }

        // even shifts j = 2*jj
        #pragma unroll
        for (int jj = 0; jj < 4; jj++) {
            fma2(accE[0][jj], hwp[jj],   pv01);
            fma2(accE[0][jj], hwp[jj+1], pv23);
            fma2(accE[1][jj], mwp[jj],   pv01);
            fma2(accE[1][jj], mwp[jj+1], pv23);
            fma2(accE[2][jj], mwp[jj],   qv01);
            fma2(accE[2][jj], mwp[jj+1], qv23);
        }
        // odd shifts j = 2*oj+1: middle pair (k=1,2) packed, k=0 and k=3 scalar
        #pragma unroll
        for (int oj = 0; oj < 3; oj++) {
            fma2(accM[0][oj], hwp[oj+1], P12);
            fma2(accM[1][oj], mwp[oj+1], P12);
            fma2(accM[2][oj], mwp[oj+1], Q12);
            const float hwj = uhi(hwp[oj]);      // hw[2oj+1]
            const float mwj = uhi(mwp[oj]);
            const float hwe = ulo(hwp[oj+2]);    // hw[2oj+4]
            const float mwe = ulo(mwp[oj+2]);
            accS[0][oj] = fmaf(hwj, pv0, fmaf(hwe, pv3, accS[0][oj]));
            accS[1][oj] = fmaf(mwj, pv0, fmaf(mwe, pv3, accS[1][oj]));
            accS[2][oj] = fmaf(mwj, qv0, fmaf(mwe, qv3, accS[2][oj]));
        }
    }

    // combine packed halves -> 21 scalars
    float a[3][7];
    #pragma unroll
    for (int s = 0; s < 3; s++) {
        #pragma unroll
        for (int jj = 0; jj < 4; jj++)
            a[s][2*jj] = ulo(accE[s][jj]) + uhi(accE[s][jj]);
        #pragma unroll
        for (int oj = 0; oj < 3; oj++)
            a[s][2*oj+1] = ulo(accM[s][oj]) + uhi(accM[s][oj]) + accS[s][oj];
    }

    // warp reduce
    #pragma unroll
    for (int s = 0; s < 3; s++)
        #pragma unroll
        for (int j = 0; j < 7; j++)
            #pragma unroll
            for (int off = 16; off; off >>= 1)
                a[s][j] += __shfl_xor_sync(0xffffffffu, a[s][j], off);

    if (lane == 0) {
        const int tile = blockIdx.y*GX + blockIdx.x;
        float* out = g_part + ((size_t)(batch*NTILE + tile)*NSH + wid*7)*3;
        #pragma unroll
        for (int j = 0; j < 7; j++) {
            out[j*3 + 0] = a[0][j];   // hp
            out[j*3 + 1] = a[2][j];   // pp
            out[j*3 + 2] = a[1][j];   // mp
        }
    }
}

// ---------------------------------------------------------------------------
// mse_kernel: assemble box sums from row sums, combine with corr partials,
// per (batch,shift) mse; min over shifts.
// ---------------------------------------------------------------------------
__global__ __launch_bounds__(64) void mse_kernel()
{
    const int b = blockIdx.x;
    const int s = threadIdx.x;   // 64 threads
    __shared__ float e_wr[12][21];
    __shared__ float ctot[21];
    __shared__ float ssp;
    __shared__ float smin[64];

    if (s < 21) {
        float c = 0.f;
        const float* base = g_rows + (size_t)b*H*21 + s;
        for (int y = 0; y < H; y++) c += base[y*21];
        ctot[s] = c;
    }
    if (s >= 40 && s < 52) {
        const int t = s - 40;
        const int y = (t < 6) ? t : (372 + t);
        const float* row = g_rows + ((size_t)b*H + y)*21;
        for (int k = 0; k < 21; k++) e_wr[t][k] = row[k];
    }
    if (s == 52) {
        float c = 0.f;
        const float* base = g_rowp + (size_t)b*H;
        for (int y = 0; y < H; y++) c += base[y];
        ssp = c;
    }
    __syncthreads();

    float mse = 3.4e38f;
    if (s < NSH) {
        const int i = s / 7, jc = s % 7;
        float Sm  = ctot[0*7 + jc];
        float SL  = ctot[1*7 + jc];
        float Shh = ctot[2*7 + jc];
        for (int y = 0; y < i; y++) {
            Sm  -= e_wr[y][0*7 + jc];
            SL  -= e_wr[y][1*7 + jc];
            Shh -= e_wr[y][2*7 + jc];
        }
        for (int t = i + 6; t < 12; t++) {
            Sm  -= e_wr[t][0*7 + jc];
            SL  -= e_wr[t][1*7 + jc];
            Shh -= e_wr[t][2*7 + jc];
        }

        float hp = 0.f, pp = 0.f, mp = 0.f;
        const float* base = g_part + ((size_t)b*NTILE*NSH + s)*3;
        for (int t = 0; t < NTILE; t++) {
            const float* q = base + (size_t)t*NSH*3;
            hp += q[0]; pp += q[1]; mp += q[2];
        }
        const float bias = (SL - ssp) / Sm;
        const float num  = Shh - 2.f*hp + pp - 2.f*bias*(SL - mp) + bias*bias*Sm;
        mse = num / Sm;
    }
    smin[s] = mse;
    __syncthreads();
    #pragma unroll
    for (int off = 32; off; off >>= 1) {
        if (s < off) smin[s] = fminf(smin[s], smin[s + off]);
        __syncthreads();
    }
    if (s == 0) g_bmin[b] = smin[0];
}

// ---------------------------------------------------------------------------
// final_kernel: mean over batches -> scalar output
// ---------------------------------------------------------------------------
__global__ __launch_bounds__(64) void final_kernel(float* __restrict__ out)
{
    __shared__ float sm[64];
    const int t = threadIdx.x;
    sm[t] = g_bmin[t];
    __syncthreads();
    #pragma unroll
    for (int off = 32; off; off >>= 1) {
        if (t < off) sm[t] += sm[t + off];
        __syncthreads();
    }
    if (t == 0) out[0] = sm[0] * (1.f / (float)Bn);
}

extern "C" void kernel_launch(void* const* d_in, const int* in_sizes, int n_in,
                              void* d_out, int out_size)
{
    const float* sr = (const float*)d_in[0];
    const float* hr = (const float*)d_in[1];
    const float* mk = (const float*)d_in[2];
    (void)in_sizes; (void)n_in; (void)out_size;

    box_kernel<<<dim3(48, Bn), 128>>>(sr, hr, mk);
    corr_kernel<<<dim3(GX, GY, Bn), 224>>>(sr, hr, mk);
    mse_kernel<<<Bn, 64>>>();
    final_kernel<<<1, 64>>>((float*)d_out);
}

// round 3
// speedup vs baseline: 1.2632x; 1.2632x over previous
#include <cuda_runtime.h>

#define Bn 64
#define H  384
#define HH (H*H)
#define BORDER 3
#define CROP 378
#define NSH 49

// corr tiling
#define TX 128
#define TY 16
#define GX 3    // ceil(378/128)
#define GY 24   // ceil(378/16)
#define NTILE (GX*GY)   // 72
#define HALO_W 136      // need 134, pad to 136 (8B/16B-safe rows)
#define HALO_H 22       // TY + 6

typedef unsigned long long ull;

// scratch (static device memory; no allocations anywhere)
__device__ float g_part[Bn*NTILE*NSH*3];  // per-tile partials: hp, pp, mp
__device__ float g_rows[Bn*H*21];         // per-row window sums (3 fields x 7 j)
__device__ float g_rowp[Bn*H];            // per-row pred sums
__device__ float g_bmin[Bn];              // per-batch min cMSE

// ---- f32x2 helpers -------------------------------------------------------
__device__ __forceinline__ ull pk2(float a, float b) {
    ull r; asm("mov.b64 %0, {%1,%2};" : "=l"(r) : "f"(a), "f"(b)); return r;
}
__device__ __forceinline__ void fma2(ull& acc, ull a, ull b) {
    asm("fma.rn.f32x2 %0, %1, %2, %0;" : "+l"(acc) : "l"(a), "l"(b));
}
__device__ __forceinline__ ull mul2(ull a, ull b) {
    ull r; asm("mul.rn.f32x2 %0, %1, %2;" : "=l"(r) : "l"(a), "l"(b)); return r;
}
__device__ __forceinline__ float ulo(ull u){ return __uint_as_float((unsigned)u); }
__device__ __forceinline__ float uhi(ull u){ return __uint_as_float((unsigned)(u>>32)); }

// ---------------------------------------------------------------------------
// box_kernel: per-row window sums for fields {m, m*h, m*h^2} (7 j-offsets)
// plus per-row pred sums. grid (48, Bn), 128 threads, 8 rows per block.
// ---------------------------------------------------------------------------
__global__ __launch_bounds__(128) void box_kernel(
    const float* __restrict__ sr, const float* __restrict__ hr,
    const float* __restrict__ mk)
{
    const int batch = blockIdx.y;
    const float* mb = mk + (size_t)batch*HH;
    const float* hb = hr + (size_t)batch*HH;
    const float* sb = sr + (size_t)batch*HH;

    const int tid  = threadIdx.x;
    const int w    = tid >> 5;
    const int lane = tid & 31;

    #pragma unroll
    for (int ry = 0; ry < 2; ry++) {
        const int y = blockIdx.x*8 + w*2 + ry;
        float tm = 0.f, tmh = 0.f, tmh2 = 0.f, tp = 0.f;
        float fm[6], fmh[6], fmh2[6];   // x = 0..5
        float bm[6], bmh[6], bmh2[6];   // x = 378..383
        #pragma unroll
        for (int c = 0; c < 12; c++) {
            const int x = c*32 + lane;
            const float m  = mb[y*H + x];
            const float h  = hb[y*H + x];
            const float mh = m*h;
            const float mh2 = mh*h;
            tm += m; tmh += mh; tmh2 += mh2;
            if (x >= BORDER && x < H-BORDER && y >= BORDER && y < H-BORDER)
                tp += sb[y*H + x] * m;
            if (c == 0) {
                #pragma unroll
                for (int j = 0; j < 6; j++) {
                    fm[j]   = __shfl_sync(0xffffffffu, m,   j);
                    fmh[j]  = __shfl_sync(0xffffffffu, mh,  j);
                    fmh2[j] = __shfl_sync(0xffffffffu, mh2, j);
                }
            }
            if (c == 11) {
                #pragma unroll
                for (int j = 0; j < 6; j++) {
                    bm[j]   = __shfl_sync(0xffffffffu, m,   26+j);
                    bmh[j]  = __shfl_sync(0xffffffffu, mh,  26+j);
                    bmh2[j] = __shfl_sync(0xffffffffu, mh2, 26+j);
                }
            }
        }
        #pragma unroll
        for (int off = 16; off; off >>= 1) {
            tm   += __shfl_xor_sync(0xffffffffu, tm,   off);
            tmh  += __shfl_xor_sync(0xffffffffu, tmh,  off);
            tmh2 += __shfl_xor_sync(0xffffffffu, tmh2, off);
            tp   += __shfl_xor_sync(0xffffffffu, tp,   off);
        }
        if (lane == 0) {
            float* out = g_rows + ((size_t)batch*H + y)*21;
            #pragma unroll
            for (int j = 0; j < 7; j++) {
                float lm = 0.f, lmh = 0.f, lmh2 = 0.f;
                float rm = 0.f, rmh = 0.f, rmh2 = 0.f;
                #pragma unroll
                for (int k = 0; k < 6; k++) {
                    if (k < j)  { lm += fm[k]; lmh += fmh[k]; lmh2 += fmh2[k]; }
                    if (k >= j) { rm += bm[k]; rmh += bmh[k]; rmh2 += bmh2[k]; }
                }
                out[0*7 + j] = tm   - lm   - rm;
                out[1*7 + j] = tmh  - lmh  - rmh;
                out[2*7 + j] = tmh2 - lmh2 - rmh2;
            }
            g_rowp[(size_t)batch*H + y] = tp;
        }
    }
}

// ---------------------------------------------------------------------------
// corr_kernel: three 7x7 correlations Shp, Spp, Smp via packed f32x2 FMA.
// 7 warps per block; warp w owns shift-row i = w. Lean register version:
// 21 ull accumulators, window pairs built once per row.
// ---------------------------------------------------------------------------
__global__ __launch_bounds__(224) void corr_kernel(
    const float* __restrict__ sr, const float* __restrict__ hr,
    const float* __restrict__ mk)
{
    __shared__ __align__(16) float s_m [HALO_H*HALO_W];
    __shared__ __align__(16) float s_mh[HALO_H*HALO_W];
    __shared__ __align__(16) float s_p [TY*TX];

    const int batch = blockIdx.z;
    const int x0 = blockIdx.x * TX;
    const int y0 = blockIdx.y * TY;
    const float* mb = mk + (size_t)batch*HH;
    const float* hb = hr + (size_t)batch*HH;
    const float* sb = sr + (size_t)batch*HH;
    const int tid = threadIdx.x;

    // halo tile of m and m*h (zero-fill OOB / pad columns)
    for (int idx = tid; idx < HALO_H*HALO_W; idx += 224) {
        const int r = idx / HALO_W, c = idx % HALO_W;
        const int y = y0 + r, x = x0 + c;
        float m = 0.f, mh = 0.f;
        if (c < 134 && y < H && x < H) {
            m  = mb[y*H + x];
            mh = m * hb[y*H + x];
        }
        s_m[idx] = m; s_mh[idx] = mh;
    }
    // pred tile (p = 0 outside valid crop)
    for (int idx = tid; idx < TY*TX; idx += 224) {
        const int r = idx / TX, c = idx % TX;
        const int y = y0 + r, x = x0 + c;
        float p = 0.f;
        if (y < CROP && x < CROP)
            p = sb[(y+BORDER)*H + x+BORDER] * mb[(y+BORDER)*H + x+BORDER];
        s_p[idx] = p;
    }
    __syncthreads();

    const int wid  = tid >> 5;      // shift row i = wid (0..6)
    const int lane = tid & 31;
    const int cb   = lane * 4;      // lane owns 4 consecutive output columns

    // acc[0]=hp (mh x p), acc[1]=mp (m x p), acc[2]=pp (m x p^2); packed pairs
    ull acc[3][7];
    #pragma unroll
    for (int s = 0; s < 3; s++)
        #pragma unroll
        for (int j = 0; j < 7; j++) acc[s][j] = 0ull;

    for (int r = 0; r < TY; r++) {
        const ull* pv = (const ull*)&s_p[r*TX + cb];
        const ull P01 = pv[0], P23 = pv[1];
        const ull Q01 = mul2(P01, P01), Q23 = mul2(P23, P23);

        const int base = (r + wid)*HALO_W + cb;
        const ull* mq = (const ull*)&s_m [base];
        const ull* hq = (const ull*)&s_mh[base];

        // window pairs W[t] = (w[t], w[t+1]); even t direct, odd t packed
        ull Wm[9], Wh[9];
        #pragma unroll
        for (int t = 0; t < 5; t++) { Wm[2*t] = mq[t]; Wh[2*t] = hq[t]; }
        #pragma unroll
        for (int t = 0; t < 4; t++) {
            Wm[2*t+1] = pk2(uhi(Wm[2*t]), ulo(Wm[2*t+2]));
            Wh[2*t+1] = pk2(uhi(Wh[2*t]), ulo(Wh[2*t+2]));
        }

        #pragma unroll
        for (int j = 0; j < 7; j++) {
            fma2(acc[0][j], Wh[j],   P01);
            fma2(acc[0][j], Wh[j+2], P23);
            fma2(acc[1][j], Wm[j],   P01);
            fma2(acc[1][j], Wm[j+2], P23);
            fma2(acc[2][j], Wm[j],   Q01);
            fma2(acc[2][j], Wm[j+2], Q23);
        }
    }

    // combine packed halves -> 21 scalars, warp reduce
    float a[3][7];
    #pragma unroll
    for (int s = 0; s < 3; s++)
        #pragma unroll
        for (int j = 0; j < 7; j++)
            a[s][j] = ulo(acc[s][j]) + uhi(acc[s][j]);

    #pragma unroll
    for (int s = 0; s < 3; s++)
        #pragma unroll
        for (int j = 0; j < 7; j++)
            #pragma unroll
            for (int off = 16; off; off >>= 1)
                a[s][j] += __shfl_xor_sync(0xffffffffu, a[s][j], off);

    if (lane == 0) {
        const int tile = blockIdx.y*GX + blockIdx.x;
        float* out = g_part + ((size_t)(batch*NTILE + tile)*NSH + wid*7)*3;
        #pragma unroll
        for (int j = 0; j < 7; j++) {
            out[j*3 + 0] = a[0][j];   // hp
            out[j*3 + 1] = a[2][j];   // pp
            out[j*3 + 2] = a[1][j];   // mp
        }
    }
}

// ---------------------------------------------------------------------------
// mse_kernel: assemble box sums from row sums (parallel column totals),
// combine with corr partials, per (batch,shift) mse; min over shifts.
// 224 threads: warp w reduces fields 3w..3w+2; warp 6 also reduces rowp.
// ---------------------------------------------------------------------------
__global__ __launch_bounds__(224) void mse_kernel()
{
    const int b = blockIdx.x;
    const int tid  = threadIdx.x;
    const int w    = tid >> 5;
    const int lane = tid & 31;

    __shared__ float e_wr[12][21];
    __shared__ float ctot[21];
    __shared__ float ssp;
    __shared__ float smin[64];

    // column totals: warp w -> fields 3w, 3w+1, 3w+2
    #pragma unroll
    for (int ff = 0; ff < 3; ff++) {
        const int f = w*3 + ff;
        float c = 0.f;
        for (int y = lane; y < H; y += 32)
            c += g_rows[((size_t)b*H + y)*21 + f];
        #pragma unroll
        for (int off = 16; off; off >>= 1)
            c += __shfl_xor_sync(0xffffffffu, c, off);
        if (lane == 0) ctot[f] = c;
    }
    // pred total (warp 6)
    if (w == 6) {
        float c = 0.f;
        for (int y = lane; y < H; y += 32)
            c += g_rowp[(size_t)b*H + y];
        #pragma unroll
        for (int off = 16; off; off >>= 1)
            c += __shfl_xor_sync(0xffffffffu, c, off);
        if (lane == 0) ssp = c;
    }
    // edge rows (first 6 and last 6)
    if (tid < 252) {
        const int t = tid / 21, k = tid % 21;
        const int y = (t < 6) ? t : (372 + t - 6 + 6);   // t<6 -> y=t, else y=372+(t-6)+6 = 372+t
        const int yy = (t < 6) ? t : (372 + t);
        (void)y;
        e_wr[t][k] = g_rows[((size_t)b*H + yy)*21 + k];
    }
    __syncthreads();

    float mse = 3.4e38f;
    if (tid < NSH) {
        const int i = tid / 7, jc = tid % 7;
        float Sm  = ctot[0*7 + jc];
        float SL  = ctot[1*7 + jc];
        float Shh = ctot[2*7 + jc];
        for (int y = 0; y < i; y++) {
            Sm  -= e_wr[y][0*7 + jc];
            SL  -= e_wr[y][1*7 + jc];
            Shh -= e_wr[y][2*7 + jc];
        }
        for (int t = i + 6; t < 12; t++) {
            Sm  -= e_wr[t][0*7 + jc];
            SL  -= e_wr[t][1*7 + jc];
            Shh -= e_wr[t][2*7 + jc];
        }

        float hp = 0.f, pp = 0.f, mp = 0.f;
        const float* base = g_part + ((size_t)b*NTILE*NSH + tid)*3;
        for (int t = 0; t < NTILE; t++) {
            const float* q = base + (size_t)t*NSH*3;
            hp += q[0]; pp += q[1]; mp += q[2];
        }
        const float bias = (SL - ssp) / Sm;
        const float num  = Shh - 2.f*hp + pp - 2.f*bias*(SL - mp) + bias*bias*Sm;
        mse = num / Sm;
    }
    if (tid < 64) smin[tid] = mse;
    __syncthreads();
    #pragma unroll
    for (int off = 32; off; off >>= 1) {
        if (tid < off) smin[tid] = fminf(smin[tid], smin[tid + off]);
        __syncthreads();
    }
    if (tid == 0) g_bmin[b] = smin[0];
}

// ---------------------------------------------------------------------------
// final_kernel: mean over batches -> scalar output
// ---------------------------------------------------------------------------
__global__ __launch_bounds__(64) void final_kernel(float* __restrict__ out)
{
    __shared__ float sm[64];
    const int t = threadIdx.x;
    sm[t] = g_bmin[t];
    __syncthreads();
    #pragma unroll
    for (int off = 32; off; off >>= 1) {
        if (t < off) sm[t] += sm[t + off];
        __syncthreads();
    }
    if (t == 0) out[0] = sm[0] * (1.f / (float)Bn);
}

extern "C" void kernel_launch(void* const* d_in, const int* in_sizes, int n_in,
                              void* d_out, int out_size)
{
    const float* sr = (const float*)d_in[0];
    const float* hr = (const float*)d_in[1];
    const float* mk = (const float*)d_in[2];
    (void)in_sizes; (void)n_in; (void)out_size;

    box_kernel<<<dim3(48, Bn), 128>>>(sr, hr, mk);
    corr_kernel<<<dim3(GX, GY, Bn), 224>>>(sr, hr, mk);
    mse_kernel<<<Bn, 224>>>();
    final_kernel<<<1, 64>>>((float*)d_out);
}

// round 4
// speedup vs baseline: 1.6099x; 1.2745x over previous
#include <cuda_runtime.h>

#define Bn 64
#define H  384
#define HH (H*H)
#define BORDER 3
#define CROP 378
#define NSH 49

// corr tiling
#define TX 128
#define TY 16
#define GX 3    // ceil(378/128)
#define GY 24   // ceil(378/16)
#define NTILE (GX*GY)   // 72
#define HALO_W 136      // need 134, pad to 136 (16B-safe rows)
#define HALO_H 22       // TY + 6

// scratch (static device memory; no allocations anywhere; zero-initialized)
__device__ float g_part[Bn*NTILE*NSH*3];  // per-tile partials: hp, pp, mp
__device__ float g_rows[Bn*H*21];         // per-row window sums (3 fields x 7 j)
__device__ float g_rowp[Bn*H];            // per-row pred sums
__device__ float g_bmin[Bn];              // per-batch min cMSE
__device__ int   g_ctr;                   // last-block-done counter (stays 0 between calls)

// ---------------------------------------------------------------------------
// box_kernel: per-row window sums for fields {m, m*h, m*h^2} (7 j-offsets)
// plus per-row pred sums. grid (48, Bn), 128 threads, 8 rows per block.
// ---------------------------------------------------------------------------
__global__ __launch_bounds__(128) void box_kernel(
    const float* __restrict__ sr, const float* __restrict__ hr,
    const float* __restrict__ mk)
{
    const int batch = blockIdx.y;
    const float* mb = mk + (size_t)batch*HH;
    const float* hb = hr + (size_t)batch*HH;
    const float* sb = sr + (size_t)batch*HH;

    const int tid  = threadIdx.x;
    const int w    = tid >> 5;
    const int lane = tid & 31;

    #pragma unroll
    for (int ry = 0; ry < 2; ry++) {
        const int y = blockIdx.x*8 + w*2 + ry;
        float tm = 0.f, tmh = 0.f, tmh2 = 0.f, tp = 0.f;
        float fm[6], fmh[6], fmh2[6];   // x = 0..5
        float bm[6], bmh[6], bmh2[6];   // x = 378..383
        #pragma unroll
        for (int c = 0; c < 12; c++) {
            const int x = c*32 + lane;
            const float m  = mb[y*H + x];
            const float h  = hb[y*H + x];
            const float mh = m*h;
            const float mh2 = mh*h;
            tm += m; tmh += mh; tmh2 += mh2;
            if (x >= BORDER && x < H-BORDER && y >= BORDER && y < H-BORDER)
                tp += sb[y*H + x] * m;
            if (c == 0) {
                #pragma unroll
                for (int j = 0; j < 6; j++) {
                    fm[j]   = __shfl_sync(0xffffffffu, m,   j);
                    fmh[j]  = __shfl_sync(0xffffffffu, mh,  j);
                    fmh2[j] = __shfl_sync(0xffffffffu, mh2, j);
                }
            }
            if (c == 11) {
                #pragma unroll
                for (int j = 0; j < 6; j++) {
                    bm[j]   = __shfl_sync(0xffffffffu, m,   26+j);
                    bmh[j]  = __shfl_sync(0xffffffffu, mh,  26+j);
                    bmh2[j] = __shfl_sync(0xffffffffu, mh2, 26+j);
                }
            }
        }
        #pragma unroll
        for (int off = 16; off; off >>= 1) {
            tm   += __shfl_xor_sync(0xffffffffu, tm,   off);
            tmh  += __shfl_xor_sync(0xffffffffu, tmh,  off);
            tmh2 += __shfl_xor_sync(0xffffffffu, tmh2, off);
            tp   += __shfl_xor_sync(0xffffffffu, tp,   off);
        }
        if (lane == 0) {
            float* out = g_rows + ((size_t)batch*H + y)*21;
            #pragma unroll
            for (int j = 0; j < 7; j++) {
                float lm = 0.f, lmh = 0.f, lmh2 = 0.f;
                float rm = 0.f, rmh = 0.f, rmh2 = 0.f;
                #pragma unroll
                for (int k = 0; k < 6; k++) {
                    if (k < j)  { lm += fm[k]; lmh += fmh[k]; lmh2 += fmh2[k]; }
                    if (k >= j) { rm += bm[k]; rmh += bmh[k]; rmh2 += bmh2[k]; }
                }
                out[0*7 + j] = tm   - lm   - rm;
                out[1*7 + j] = tmh  - lmh  - rmh;
                out[2*7 + j] = tmh2 - lmh2 - rmh2;
            }
            g_rowp[(size_t)batch*H + y] = tp;
        }
    }
}

// ---------------------------------------------------------------------------
// corr_kernel: the three 7x7 correlations Shp, Spp, Smp (tile partials).
// 7 warps per block; warp w owns shift-row i = w. Scalar FFMA (R1-proven).
// ---------------------------------------------------------------------------
__global__ __launch_bounds__(224) void corr_kernel(
    const float* __restrict__ sr, const float* __restrict__ hr,
    const float* __restrict__ mk)
{
    __shared__ __align__(16) float s_m [HALO_H*HALO_W];
    __shared__ __align__(16) float s_mh[HALO_H*HALO_W];
    __shared__ __align__(16) float s_p [TY*TX];
    __shared__ __align__(16) float s_pp[TY*TX];

    const int batch = blockIdx.z;
    const int x0 = blockIdx.x * TX;
    const int y0 = blockIdx.y * TY;
    const float* mb = mk + (size_t)batch*HH;
    const float* hb = hr + (size_t)batch*HH;
    const float* sb = sr + (size_t)batch*HH;
    const int tid = threadIdx.x;

    // halo tile of m and m*h (zero-fill OOB / pad columns)
    for (int idx = tid; idx < HALO_H*HALO_W; idx += 224) {
        const int r = idx / HALO_W, c = idx % HALO_W;
        const int y = y0 + r, x = x0 + c;
        float m = 0.f, mh = 0.f;
        if (c < 134 && y < H && x < H) {
            m  = mb[y*H + x];
            mh = m * hb[y*H + x];
        }
        s_m[idx] = m; s_mh[idx] = mh;
    }
    // pred tile (p = 0 outside valid crop => no flow predicates needed later)
    for (int idx = tid; idx < TY*TX; idx += 224) {
        const int r = idx / TX, c = idx % TX;
        const int y = y0 + r, x = x0 + c;
        float p = 0.f;
        if (y < CROP && x < CROP)
            p = sb[(y+BORDER)*H + x+BORDER] * mb[(y+BORDER)*H + x+BORDER];
        s_p[idx] = p; s_pp[idx] = p*p;
    }
    __syncthreads();

    const int wid  = tid >> 5;      // shift row i = wid (0..6)
    const int lane = tid & 31;
    const int cb   = lane * 4;      // lane owns 4 consecutive output columns

    float a_hp[7], a_pp[7], a_mp[7];
    #pragma unroll
    for (int j = 0; j < 7; j++) { a_hp[j]=0.f; a_pp[j]=0.f; a_mp[j]=0.f; }

    for (int r = 0; r < TY; r++) {
        const float4 p4 = *(const float4*)&s_p [r*TX + cb];
        const float4 q4 = *(const float4*)&s_pp[r*TX + cb];
        const float pv[4] = {p4.x, p4.y, p4.z, p4.w};
        const float qv[4] = {q4.x, q4.y, q4.z, q4.w};

        const int hbase = (r + wid)*HALO_W + cb;
        float mw[10], hw[10];
        {
            float4 t; float2 u;
            t = *(const float4*)&s_m[hbase];    mw[0]=t.x; mw[1]=t.y; mw[2]=t.z; mw[3]=t.w;
            t = *(const float4*)&s_m[hbase+4];  mw[4]=t.x; mw[5]=t.y; mw[6]=t.z; mw[7]=t.w;
            u = *(const float2*)&s_m[hbase+8];  mw[8]=u.x; mw[9]=u.y;
            t = *(const float4*)&s_mh[hbase];   hw[0]=t.x; hw[1]=t.y; hw[2]=t.z; hw[3]=t.w;
            t = *(const float4*)&s_mh[hbase+4]; hw[4]=t.x; hw[5]=t.y; hw[6]=t.z; hw[7]=t.w;
            u = *(const float2*)&s_mh[hbase+8]; hw[8]=u.x; hw[9]=u.y;
        }
        #pragma unroll
        for (int j = 0; j < 7; j++) {
            #pragma unroll
            for (int k = 0; k < 4; k++) {
                a_hp[j] = fmaf(hw[j+k], pv[k], a_hp[j]);
                a_mp[j] = fmaf(mw[j+k], pv[k], a_mp[j]);
                a_pp[j] = fmaf(mw[j+k], qv[k], a_pp[j]);
            }
        }
    }

    // warp reduce 21 accumulators
    #pragma unroll
    for (int j = 0; j < 7; j++) {
        #pragma unroll
        for (int off = 16; off; off >>= 1) {
            a_hp[j] += __shfl_xor_sync(0xffffffffu, a_hp[j], off);
            a_pp[j] += __shfl_xor_sync(0xffffffffu, a_pp[j], off);
            a_mp[j] += __shfl_xor_sync(0xffffffffu, a_mp[j], off);
        }
    }
    if (lane == 0) {
        const int tile = blockIdx.y*GX + blockIdx.x;
        float* out = g_part + ((size_t)(batch*NTILE + tile)*NSH + wid*7)*3;
        #pragma unroll
        for (int j = 0; j < 7; j++) {
            out[j*3 + 0] = a_hp[j];
            out[j*3 + 1] = a_pp[j];
            out[j*3 + 2] = a_mp[j];
        }
    }
}

// ---------------------------------------------------------------------------
// mse_kernel: assemble box sums from row sums (parallel column totals),
// combine with corr partials, per (batch,shift) mse; min over shifts.
// Last finished block also reduces the 64 per-batch minima to the output
// scalar (deterministic: single block, fixed order).
// ---------------------------------------------------------------------------
__global__ __launch_bounds__(224) void mse_kernel(float* __restrict__ out)
{
    const int b = blockIdx.x;
    const int tid  = threadIdx.x;
    const int w    = tid >> 5;
    const int lane = tid & 31;

    __shared__ float e_wr[12][21];
    __shared__ float ctot[21];
    __shared__ float ssp;
    __shared__ float smin[64];
    __shared__ int   is_last;

    // column totals: warp w -> fields 3w, 3w+1, 3w+2
    #pragma unroll
    for (int ff = 0; ff < 3; ff++) {
        const int f = w*3 + ff;
        float c = 0.f;
        for (int y = lane; y < H; y += 32)
            c += g_rows[((size_t)b*H + y)*21 + f];
        #pragma unroll
        for (int off = 16; off; off >>= 1)
            c += __shfl_xor_sync(0xffffffffu, c, off);
        if (lane == 0) ctot[f] = c;
    }
    // pred total (warp 6)
    if (w == 6) {
        float c = 0.f;
        for (int y = lane; y < H; y += 32)
            c += g_rowp[(size_t)b*H + y];
        #pragma unroll
        for (int off = 16; off; off >>= 1)
            c += __shfl_xor_sync(0xffffffffu, c, off);
        if (lane == 0) ssp = c;
    }
    // edge rows (first 6 and last 6) — strided (252 items, 224 threads)
    for (int t2 = tid; t2 < 252; t2 += 224) {
        const int t = t2 / 21, k = t2 % 21;
        const int yy = (t < 6) ? t : (372 + t);
        e_wr[t][k] = g_rows[((size_t)b*H + yy)*21 + k];
    }
    __syncthreads();

    float mse = 3.4e38f;
    if (tid < NSH) {
        const int i = tid / 7, jc = tid % 7;
        float Sm  = ctot[0*7 + jc];
        float SL  = ctot[1*7 + jc];
        float Shh = ctot[2*7 + jc];
        for (int y = 0; y < i; y++) {
            Sm  -= e_wr[y][0*7 + jc];
            SL  -= e_wr[y][1*7 + jc];
            Shh -= e_wr[y][2*7 + jc];
        }
        for (int t = i + 6; t < 12; t++) {
            Sm  -= e_wr[t][0*7 + jc];
            SL  -= e_wr[t][1*7 + jc];
            Shh -= e_wr[t][2*7 + jc];
        }

        float hp = 0.f, pp = 0.f, mp = 0.f;
        const float* base = g_part + ((size_t)b*NTILE*NSH + tid)*3;
        for (int t = 0; t < NTILE; t++) {
            const float* q = base + (size_t)t*NSH*3;
            hp += q[0]; pp += q[1]; mp += q[2];
        }
        const float bias = (SL - ssp) / Sm;
        const float num  = Shh - 2.f*hp + pp - 2.f*bias*(SL - mp) + bias*bias*Sm;
        mse = num / Sm;
    }
    if (tid < 64) smin[tid] = mse;
    __syncthreads();
    #pragma unroll
    for (int off = 32; off; off >>= 1) {
        if (tid < off) smin[tid] = fminf(smin[tid], smin[tid + off]);
        __syncthreads();
    }
    if (tid == 0) {
        g_bmin[b] = smin[0];
        __threadfence();
        is_last = (atomicAdd(&g_ctr, 1) == Bn - 1) ? 1 : 0;
    }
    __syncthreads();

    if (is_last) {
        __threadfence();          // acquire all g_bmin writes
        if (tid < 64) smin[tid] = g_bmin[tid];
        __syncthreads();
        #pragma unroll
        for (int off = 32; off; off >>= 1) {
            if (tid < off) smin[tid] += smin[tid + off];
            __syncthreads();
        }
        if (tid == 0) {
            out[0] = smin[0] * (1.f / (float)Bn);
            g_ctr = 0;            // leave counter clean for next replay
        }
    }
}

extern "C" void kernel_launch(void* const* d_in, const int* in_sizes, int n_in,
                              void* d_out, int out_size)
{
    const float* sr = (const float*)d_in[0];
    const float* hr = (const float*)d_in[1];
    const float* mk = (const float*)d_in[2];
    (void)in_sizes; (void)n_in; (void)out_size;

    box_kernel<<<dim3(48, Bn), 128>>>(sr, hr, mk);
    corr_kernel<<<dim3(GX, GY, Bn), 224>>>(sr, hr, mk);
    mse_kernel<<<Bn, 224>>>((float*)d_out);
}

// round 6
// speedup vs baseline: 1.7417x; 1.0818x over previous
#include <cuda_runtime.h>

#define Bn 64
#define H  384
#define HH (H*H)
#define BORDER 3
#define CROP 378
#define NSH 49

// corr tiling: 3 x 24 tiles exactly partition 384 x 384 (owned 128 x 16 each)
#define TX 128
#define TY 16
#define GX 3
#define GY 24
#define NTILE (GX*GY)   // 72
#define HALO_W 136      // need 134, pad to 136 (16B-safe rows)
#define HALO_H 22       // TY + 6
#define NT 224          // threads per corr/mse block

// scratch (static device memory; zero-initialized; no allocations anywhere)
__device__ float g_part [Bn*NTILE*NSH*3];   // corr partials: hp, pp, mp
__device__ float g_rsum [Bn*H*3*3];         // per (b,y,bx): {Sm,SL,Shh} partial
__device__ float g_eL   [Bn*H*3*6];         // left edge cols 0..5 per field
__device__ float g_eR   [Bn*H*3*6];         // right edge cols 378..383 per field
__device__ float g_ppart[Bn*NTILE];         // per-tile sum of pred
__device__ float g_bmin [Bn];               // per-batch min cMSE
__device__ int   g_ctr;                     // last-block counter (returns to 0)

// ---------------------------------------------------------------------------
// corr_kernel: three 7x7 correlations Shp, Spp, Smp (tile partials) + fused
// box row-sum partials. 7 warps; warp w owns shift-row i = w.
// ---------------------------------------------------------------------------
__global__ __launch_bounds__(NT) void corr_kernel(
    const float* __restrict__ sr, const float* __restrict__ hr,
    const float* __restrict__ mk)
{
    __shared__ __align__(16) float s_m [HALO_H*HALO_W];
    __shared__ __align__(16) float s_mh[HALO_H*HALO_W];
    __shared__ __align__(16) float s_p [TY*TX];
    __shared__ __align__(16) float s_pp[TY*TX];
    __shared__ float s_red[8];

    const int batch = blockIdx.z;
    const int bxi = blockIdx.x, byi = blockIdx.y;
    const int x0 = bxi * TX;
    const int y0 = byi * TY;
    const float* mb = mk + (size_t)batch*HH;
    const float* hb = hr + (size_t)batch*HH;
    const float* sb = sr + (size_t)batch*HH;
    const int tid  = threadIdx.x;
    const int wid  = tid >> 5;
    const int lane = tid & 31;

    // ---- halo tiles of m and m*h via float4 (rows 22, 34 float4 cols) ----
    for (int idx = tid; idx < HALO_H*34; idx += NT) {
        const int r  = idx / 34, c4 = idx % 34;
        const int y  = y0 + r, x = x0 + c4*4;
        float4 m4 = make_float4(0.f,0.f,0.f,0.f);
        float4 h4 = make_float4(0.f,0.f,0.f,0.f);
        if (y < H && x + 3 < H) {
            m4 = *(const float4*)&mb[y*H + x];
            h4 = *(const float4*)&hb[y*H + x];
            if (c4 == 33) { m4.z = 0.f; m4.w = 0.f; }   // cols 134,135 are pad
        }
        float4 l4;
        l4.x = m4.x*h4.x; l4.y = m4.y*h4.y; l4.z = m4.z*h4.z; l4.w = m4.w*h4.w;
        *(float4*)&s_m [r*HALO_W + c4*4] = m4;
        *(float4*)&s_mh[r*HALO_W + c4*4] = l4;
    }
    __syncthreads();

    // ---- fused box partials from owned 16x128 region ----
    for (int r = wid; r < TY; r += 7) {
        const float4 m4 = *(const float4*)&s_m [r*HALO_W + lane*4];
        const float4 l4 = *(const float4*)&s_mh[r*HALO_W + lane*4];
        float sm = m4.x + m4.y + m4.z + m4.w;
        float sl = l4.x + l4.y + l4.z + l4.w;
        float sh = l4.x*l4.x + l4.y*l4.y + l4.z*l4.z + l4.w*l4.w;  // m*h^2 (m binary)
        #pragma unroll
        for (int off = 16; off; off >>= 1) {
            sm += __shfl_xor_sync(0xffffffffu, sm, off);
            sl += __shfl_xor_sync(0xffffffffu, sl, off);
            sh += __shfl_xor_sync(0xffffffffu, sh, off);
        }
        if (lane == 0) {
            float* q = g_rsum + (((size_t)batch*H + (y0+r))*3 + bxi)*3;
            q[0] = sm; q[1] = sl; q[2] = sh;
        }
    }
    if (bxi == 0 && tid < 96) {
        const int r = tid / 6, c = tid % 6;
        const float m = s_m[r*HALO_W + c], l = s_mh[r*HALO_W + c];
        float* q = g_eL + ((size_t)batch*H + (y0+r))*18;
        q[0*6+c] = m; q[1*6+c] = l; q[2*6+c] = l*l;
    }
    if (bxi == 2 && tid < 96) {
        const int r = tid / 6, c = tid % 6;
        const float m = s_m[r*HALO_W + 122 + c], l = s_mh[r*HALO_W + 122 + c];
        float* q = g_eR + ((size_t)batch*H + (y0+r))*18;
        q[0*6+c] = m; q[1*6+c] = l; q[2*6+c] = l*l;
    }

    // ---- pred tile from sr (global) * mask (smem); accumulate sum(pred) ----
    float tp = 0.f;
    for (int idx = tid; idx < TY*TX; idx += NT) {
        const int r = idx >> 7, c = idx & 127;
        const int y = y0 + r, x = x0 + c;   // pred (crop) coordinates
        float p = 0.f;
        if (y < CROP && x < CROP)
            p = sb[(y+BORDER)*H + (x+BORDER)] * s_m[(r+BORDER)*HALO_W + (c+BORDER)];
        s_p[idx] = p; s_pp[idx] = p*p;
        tp += p;
    }
    #pragma unroll
    for (int off = 16; off; off >>= 1)
        tp += __shfl_xor_sync(0xffffffffu, tp, off);
    if (lane == 0) s_red[wid] = tp;
    __syncthreads();
    if (tid == 0) {
        float s = 0.f;
        #pragma unroll
        for (int k = 0; k < 7; k++) s += s_red[k];
        g_ppart[(size_t)batch*NTILE + byi*GX + bxi] = s;
    }

    // ---- main correlation loop (R1-proven scalar core) ----
    const int cb = lane * 4;
    float a_hp[7], a_pp[7], a_mp[7];
    #pragma unroll
    for (int j = 0; j < 7; j++) { a_hp[j]=0.f; a_pp[j]=0.f; a_mp[j]=0.f; }

    for (int r = 0; r < TY; r++) {
        const float4 p4 = *(const float4*)&s_p [r*TX + cb];
        const float4 q4 = *(const float4*)&s_pp[r*TX + cb];
        const float pv[4] = {p4.x, p4.y, p4.z, p4.w};
        const float qv[4] = {q4.x, q4.y, q4.z, q4.w};

        const int hbase = (r + wid)*HALO_W + cb;
        float mw[10], hw[10];
        {
            float4 t; float2 u;
            t = *(const float4*)&s_m[hbase];    mw[0]=t.x; mw[1]=t.y; mw[2]=t.z; mw[3]=t.w;
            t = *(const float4*)&s_m[hbase+4];  mw[4]=t.x; mw[5]=t.y; mw[6]=t.z; mw[7]=t.w;
            u = *(const float2*)&s_m[hbase+8];  mw[8]=u.x; mw[9]=u.y;
            t = *(const float4*)&s_mh[hbase];   hw[0]=t.x; hw[1]=t.y; hw[2]=t.z; hw[3]=t.w;
            t = *(const float4*)&s_mh[hbase+4]; hw[4]=t.x; hw[5]=t.y; hw[6]=t.z; hw[7]=t.w;
            u = *(const float2*)&s_mh[hbase+8]; hw[8]=u.x; hw[9]=u.y;
        }
        #pragma unroll
        for (int j = 0; j < 7; j++) {
            #pragma unroll
            for (int k = 0; k < 4; k++) {
                a_hp[j] = fmaf(hw[j+k], pv[k], a_hp[j]);
                a_mp[j] = fmaf(mw[j+k], pv[k], a_mp[j]);
                a_pp[j] = fmaf(mw[j+k], qv[k], a_pp[j]);
            }
        }
    }

    #pragma unroll
    for (int j = 0; j < 7; j++) {
        #pragma unroll
        for (int off = 16; off; off >>= 1) {
            a_hp[j] += __shfl_xor_sync(0xffffffffu, a_hp[j], off);
            a_pp[j] += __shfl_xor_sync(0xffffffffu, a_pp[j], off);
            a_mp[j] += __shfl_xor_sync(0xffffffffu, a_mp[j], off);
        }
    }
    if (lane == 0) {
        const int tile = byi*GX + bxi;
        float* out = g_part + ((size_t)(batch*NTILE + tile)*NSH + wid*7)*3;
        #pragma unroll
        for (int j = 0; j < 7; j++) {
            out[j*3 + 0] = a_hp[j];
            out[j*3 + 1] = a_pp[j];
            out[j*3 + 2] = a_mp[j];
        }
    }
}

// ---------------------------------------------------------------------------
// mse_kernel: assemble window sums from row partials + edges, combine with
// corr partials; per-shift mse; min over shifts; last block -> mean -> out.
// ---------------------------------------------------------------------------
__device__ __forceinline__ float window_val(int b, int y, int f, int j)
{
    const float* q  = g_rsum + (((size_t)b*H + y)*3)*3;
    float T = q[f] + q[3+f] + q[6+f];
    const float* gl = g_eL + ((size_t)b*H + y)*18 + f*6;
    const float* gr = g_eR + ((size_t)b*H + y)*18 + f*6;
    for (int k = 0; k < j; k++) T -= gl[k];
    for (int k = j; k < 6; k++) T -= gr[k];
    return T;
}

__global__ __launch_bounds__(NT) void mse_kernel(float* __restrict__ out)
{
    const int b = blockIdx.x;
    const int tid  = threadIdx.x;
    const int w    = tid >> 5;
    const int lane = tid & 31;

    __shared__ float ctot[3][7];
    __shared__ float e_w[12][3][7];
    __shared__ float ssp;
    __shared__ float smin[64];
    __shared__ int   is_last;

    // column totals over all rows: warp w handles j = w
    {
        float acc0 = 0.f, acc1 = 0.f, acc2 = 0.f;
        for (int y = lane; y < H; y += 32) {
            acc0 += window_val(b, y, 0, w);
            acc1 += window_val(b, y, 1, w);
            acc2 += window_val(b, y, 2, w);
        }
        #pragma unroll
        for (int off = 16; off; off >>= 1) {
            acc0 += __shfl_xor_sync(0xffffffffu, acc0, off);
            acc1 += __shfl_xor_sync(0xffffffffu, acc1, off);
            acc2 += __shfl_xor_sync(0xffffffffu, acc2, off);
        }
        if (lane == 0) { ctot[0][w] = acc0; ctot[1][w] = acc1; ctot[2][w] = acc2; }
    }
    // edge rows (first 6 and last 6): 12 x 3 x 7 = 252 combos
    for (int t = tid; t < 252; t += NT) {
        const int r = t / 21, rest = t % 21;
        const int f = rest / 7, j = rest % 7;
        const int y = (r < 6) ? r : (372 + r);
        e_w[r][f][j] = window_val(b, y, f, j);
    }
    // pred total
    if (w == 0) {
        float c = 0.f;
        for (int t = lane; t < NTILE; t += 32) c += g_ppart[(size_t)b*NTILE + t];
        #pragma unroll
        for (int off = 16; off; off >>= 1)
            c += __shfl_xor_sync(0xffffffffu, c, off);
        if (lane == 0) ssp = c;
    }
    __syncthreads();

    float mse = 3.4e38f;
    if (tid < NSH) {
        const int i = tid / 7, jc = tid % 7;
        float Sm  = ctot[0][jc];
        float SL  = ctot[1][jc];
        float Shh = ctot[2][jc];
        for (int y = 0; y < i; y++) {
            Sm  -= e_w[y][0][jc];
            SL  -= e_w[y][1][jc];
            Shh -= e_w[y][2][jc];
        }
        for (int t = i + 6; t < 12; t++) {
            Sm  -= e_w[t][0][jc];
            SL  -= e_w[t][1][jc];
            Shh -= e_w[t][2][jc];
        }

        float hp = 0.f, pp = 0.f, mp = 0.f;
        const float* base = g_part + ((size_t)b*NTILE*NSH + tid)*3;
        for (int t = 0; t < NTILE; t++) {
            const float* q = base + (size_t)t*NSH*3;
            hp += q[0]; pp += q[1]; mp += q[2];
        }
        const float bias = (SL - ssp) / Sm;
        const float num  = Shh - 2.f*hp + pp - 2.f*bias*(SL - mp) + bias*bias*Sm;
        mse = num / Sm;
    }
    if (tid < 64) smin[tid] = mse;
    __syncthreads();
    #pragma unroll
    for (int off = 32; off; off >>= 1) {
        if (tid < off) smin[tid] = fminf(smin[tid], smin[tid + off]);
        __syncthreads();
    }
    if (tid == 0) {
        g_bmin[b] = smin[0];
        __threadfence();
        is_last = (atomicAdd(&g_ctr, 1) == Bn - 1) ? 1 : 0;
    }
    __syncthreads();

    if (is_last) {
        __threadfence();
        if (tid < 64) smin[tid] = g_bmin[tid];
        __syncthreads();
        #pragma unroll
        for (int off = 32; off; off >>= 1) {
            if (tid < off) smin[tid] += smin[tid + off];
            __syncthreads();
        }
        if (tid == 0) {
            out[0] = smin[0] * (1.f / (float)Bn);
            g_ctr = 0;
        }
    }
}

extern "C" void kernel_launch(void* const* d_in, const int* in_sizes, int n_in,
                              void* d_out, int out_size)
{
    const float* sr = (const float*)d_in[0];
    const float* hr = (const float*)d_in[1];
    const float* mk = (const float*)d_in[2];
    (void)in_sizes; (void)n_in; (void)out_size;

    corr_kernel<<<dim3(GX, GY, Bn), NT>>>(sr, hr, mk);
    mse_kernel<<<Bn, NT>>>((float*)d_out);
}

// round 7
// speedup vs baseline: 1.7498x; 1.0047x over previous
#include <cuda_runtime.h>

#define Bn 64
#define H  384
#define HH (H*H)
#define BORDER 3
#define CROP 378
#define NSH 49

// corr tiling: 3 x 24 tiles exactly partition 384 x 384 (owned 128 x 16 each)
#define TX 128
#define TY 16
#define GX 3
#define GY 24
#define NTILE (GX*GY)   // 72
#define HALO_W 136      // need 134, pad to 136 (16B-safe rows)
#define HALO_H 22       // TY + 6
#define NT 224          // threads per corr/mse block

// scratch (static device memory; zero-initialized; no allocations anywhere)
__device__ float g_part [Bn*NTILE*NSH*3];   // corr partials: hp, pp, mp
__device__ float g_rsum [Bn*H*3*3];         // per (b,y,bx): {Sm,SL,Shh} partial
__device__ float g_eL   [Bn*H*3*6];         // left edge cols 0..5 per field
__device__ float g_eR   [Bn*H*3*6];         // right edge cols 378..383 per field
__device__ float g_ppart[Bn*NTILE];         // per-tile sum of pred
__device__ float g_bmin [Bn];               // per-batch min cMSE
__device__ int   g_ctr;                     // last-block counter (returns to 0)

// ---------------------------------------------------------------------------
// corr_kernel: three 7x7 correlations Shp, Spp, Smp (tile partials) + fused
// box row-sum partials. 7 warps; warp w owns shift-row i = w.
// ---------------------------------------------------------------------------
__global__ __launch_bounds__(NT) void corr_kernel(
    const float* __restrict__ sr, const float* __restrict__ hr,
    const float* __restrict__ mk)
{
    __shared__ __align__(16) float s_m [HALO_H*HALO_W];
    __shared__ __align__(16) float s_mh[HALO_H*HALO_W];
    __shared__ __align__(16) float s_p [TY*TX];
    __shared__ __align__(16) float s_pp[TY*TX];
    __shared__ float s_red[8];

    const int batch = blockIdx.z;
    const int bxi = blockIdx.x, byi = blockIdx.y;
    const int x0 = bxi * TX;
    const int y0 = byi * TY;
    const float* mb = mk + (size_t)batch*HH;
    const float* hb = hr + (size_t)batch*HH;
    const float* sb = sr + (size_t)batch*HH;
    const int tid  = threadIdx.x;
    const int wid  = tid >> 5;
    const int lane = tid & 31;

    // ---- halo tiles of m and m*h via float4 (rows 22, 34 float4 cols) ----
    for (int idx = tid; idx < HALO_H*34; idx += NT) {
        const int r  = idx / 34, c4 = idx % 34;
        const int y  = y0 + r, x = x0 + c4*4;
        float4 m4 = make_float4(0.f,0.f,0.f,0.f);
        float4 h4 = make_float4(0.f,0.f,0.f,0.f);
        if (y < H && x + 3 < H) {
            m4 = *(const float4*)&mb[y*H + x];
            h4 = *(const float4*)&hb[y*H + x];
            if (c4 == 33) { m4.z = 0.f; m4.w = 0.f; }   // cols 134,135 are pad
        }
        float4 l4;
        l4.x = m4.x*h4.x; l4.y = m4.y*h4.y; l4.z = m4.z*h4.z; l4.w = m4.w*h4.w;
        *(float4*)&s_m [r*HALO_W + c4*4] = m4;
        *(float4*)&s_mh[r*HALO_W + c4*4] = l4;
    }
    __syncthreads();

    // ---- fused box partials from owned 16x128 region ----
    for (int r = wid; r < TY; r += 7) {
        const float4 m4 = *(const float4*)&s_m [r*HALO_W + lane*4];
        const float4 l4 = *(const float4*)&s_mh[r*HALO_W + lane*4];
        float sm = m4.x + m4.y + m4.z + m4.w;
        float sl = l4.x + l4.y + l4.z + l4.w;
        float sh = l4.x*l4.x + l4.y*l4.y + l4.z*l4.z + l4.w*l4.w;  // m*h^2 (m binary)
        #pragma unroll
        for (int off = 16; off; off >>= 1) {
            sm += __shfl_xor_sync(0xffffffffu, sm, off);
            sl += __shfl_xor_sync(0xffffffffu, sl, off);
            sh += __shfl_xor_sync(0xffffffffu, sh, off);
        }
        if (lane == 0) {
            float* q = g_rsum + (((size_t)batch*H + (y0+r))*3 + bxi)*3;
            q[0] = sm; q[1] = sl; q[2] = sh;
        }
    }
    if (bxi == 0 && tid < 96) {
        const int r = tid / 6, c = tid % 6;
        const float m = s_m[r*HALO_W + c], l = s_mh[r*HALO_W + c];
        float* q = g_eL + ((size_t)batch*H + (y0+r))*18;
        q[0*6+c] = m; q[1*6+c] = l; q[2*6+c] = l*l;
    }
    if (bxi == 2 && tid < 96) {
        const int r = tid / 6, c = tid % 6;
        const float m = s_m[r*HALO_W + 122 + c], l = s_mh[r*HALO_W + 122 + c];
        float* q = g_eR + ((size_t)batch*H + (y0+r))*18;
        q[0*6+c] = m; q[1*6+c] = l; q[2*6+c] = l*l;
    }

    // ---- pred tile from sr (global) * mask (smem); accumulate sum(pred) ----
    float tp = 0.f;
    for (int idx = tid; idx < TY*TX; idx += NT) {
        const int r = idx >> 7, c = idx & 127;
        const int y = y0 + r, x = x0 + c;   // pred (crop) coordinates
        float p = 0.f;
        if (y < CROP && x < CROP)
            p = sb[(y+BORDER)*H + (x+BORDER)] * s_m[(r+BORDER)*HALO_W + (c+BORDER)];
        s_p[idx] = p; s_pp[idx] = p*p;
        tp += p;
    }
    #pragma unroll
    for (int off = 16; off; off >>= 1)
        tp += __shfl_xor_sync(0xffffffffu, tp, off);
    if (lane == 0) s_red[wid] = tp;
    __syncthreads();
    if (tid == 0) {
        float s = 0.f;
        #pragma unroll
        for (int k = 0; k < 7; k++) s += s_red[k];
        g_ppart[(size_t)batch*NTILE + byi*GX + bxi] = s;
    }

    // ---- main correlation loop (R1-proven scalar core) ----
    const int cb = lane * 4;
    float a_hp[7], a_pp[7], a_mp[7];
    #pragma unroll
    for (int j = 0; j < 7; j++) { a_hp[j]=0.f; a_pp[j]=0.f; a_mp[j]=0.f; }

    for (int r = 0; r < TY; r++) {
        const float4 p4 = *(const float4*)&s_p [r*TX + cb];
        const float4 q4 = *(const float4*)&s_pp[r*TX + cb];
        const float pv[4] = {p4.x, p4.y, p4.z, p4.w};
        const float qv[4] = {q4.x, q4.y, q4.z, q4.w};

        const int hbase = (r + wid)*HALO_W + cb;
        float mw[10], hw[10];
        {
            float4 t; float2 u;
            t = *(const float4*)&s_m[hbase];    mw[0]=t.x; mw[1]=t.y; mw[2]=t.z; mw[3]=t.w;
            t = *(const float4*)&s_m[hbase+4];  mw[4]=t.x; mw[5]=t.y; mw[6]=t.z; mw[7]=t.w;
            u = *(const float2*)&s_m[hbase+8];  mw[8]=u.x; mw[9]=u.y;
            t = *(const float4*)&s_mh[hbase];   hw[0]=t.x; hw[1]=t.y; hw[2]=t.z; hw[3]=t.w;
            t = *(const float4*)&s_mh[hbase+4]; hw[4]=t.x; hw[5]=t.y; hw[6]=t.z; hw[7]=t.w;
            u = *(const float2*)&s_mh[hbase+8]; hw[8]=u.x; hw[9]=u.y;
        }
        #pragma unroll
        for (int j = 0; j < 7; j++) {
            #pragma unroll
            for (int k = 0; k < 4; k++) {
                a_hp[j] = fmaf(hw[j+k], pv[k], a_hp[j]);
                a_mp[j] = fmaf(mw[j+k], pv[k], a_mp[j]);
                a_pp[j] = fmaf(mw[j+k], qv[k], a_pp[j]);
            }
        }
    }

    #pragma unroll
    for (int j = 0; j < 7; j++) {
        #pragma unroll
        for (int off = 16; off; off >>= 1) {
            a_hp[j] += __shfl_xor_sync(0xffffffffu, a_hp[j], off);
            a_pp[j] += __shfl_xor_sync(0xffffffffu, a_pp[j], off);
            a_mp[j] += __shfl_xor_sync(0xffffffffu, a_mp[j], off);
        }
    }
    if (lane == 0) {
        const int tile = byi*GX + bxi;
        float* out = g_part + ((size_t)(batch*NTILE + tile)*NSH + wid*7)*3;
        #pragma unroll
        for (int j = 0; j < 7; j++) {
            out[j*3 + 0] = a_hp[j];
            out[j*3 + 1] = a_pp[j];
            out[j*3 + 2] = a_mp[j];
        }
    }
}

// ---------------------------------------------------------------------------
// mse_kernel: assemble window sums from row partials + edges, combine with
// corr partials; per-shift mse; min over shifts; last block -> mean -> out.
// ---------------------------------------------------------------------------
__device__ __forceinline__ float window_val(int b, int y, int f, int j)
{
    const float* q  = g_rsum + (((size_t)b*H + y)*3)*3;
    float T = q[f] + q[3+f] + q[6+f];
    const float* gl = g_eL + ((size_t)b*H + y)*18 + f*6;
    const float* gr = g_eR + ((size_t)b*H + y)*18 + f*6;
    for (int k = 0; k < j; k++) T -= gl[k];
    for (int k = j; k < 6; k++) T -= gr[k];
    return T;
}

__global__ __launch_bounds__(NT) void mse_kernel(float* __restrict__ out)
{
    const int b = blockIdx.x;
    const int tid  = threadIdx.x;
    const int w    = tid >> 5;
    const int lane = tid & 31;

    __shared__ float ctot[3][7];
    __shared__ float e_w[12][3][7];
    __shared__ float ssp;
    __shared__ float smin[64];
    __shared__ int   is_last;

    // column totals over all rows: warp w handles j = w
    {
        float acc0 = 0.f, acc1 = 0.f, acc2 = 0.f;
        for (int y = lane; y < H; y += 32) {
            acc0 += window_val(b, y, 0, w);
            acc1 += window_val(b, y, 1, w);
            acc2 += window_val(b, y, 2, w);
        }
        #pragma unroll
        for (int off = 16; off; off >>= 1) {
            acc0 += __shfl_xor_sync(0xffffffffu, acc0, off);
            acc1 += __shfl_xor_sync(0xffffffffu, acc1, off);
            acc2 += __shfl_xor_sync(0xffffffffu, acc2, off);
        }
        if (lane == 0) { ctot[0][w] = acc0; ctot[1][w] = acc1; ctot[2][w] = acc2; }
    }
    // edge rows (first 6 and last 6): 12 x 3 x 7 = 252 combos
    for (int t = tid; t < 252; t += NT) {
        const int r = t / 21, rest = t % 21;
        const int f = rest / 7, j = rest % 7;
        const int y = (r < 6) ? r : (372 + r);
        e_w[r][f][j] = window_val(b, y, f, j);
    }
    // pred total
    if (w == 0) {
        float c = 0.f;
        for (int t = lane; t < NTILE; t += 32) c += g_ppart[(size_t)b*NTILE + t];
        #pragma unroll
        for (int off = 16; off; off >>= 1)
            c += __shfl_xor_sync(0xffffffffu, c, off);
        if (lane == 0) ssp = c;
    }
    __syncthreads();

    float mse = 3.4e38f;
    if (tid < NSH) {
        const int i = tid / 7, jc = tid % 7;
        float Sm  = ctot[0][jc];
        float SL  = ctot[1][jc];
        float Shh = ctot[2][jc];
        for (int y = 0; y < i; y++) {
            Sm  -= e_w[y][0][jc];
            SL  -= e_w[y][1][jc];
            Shh -= e_w[y][2][jc];
        }
        for (int t = i + 6; t < 12; t++) {
            Sm  -= e_w[t][0][jc];
            SL  -= e_w[t][1][jc];
            Shh -= e_w[t][2][jc];
        }

        float hp = 0.f, pp = 0.f, mp = 0.f;
        const float* base = g_part + ((size_t)b*NTILE*NSH + tid)*3;
        for (int t = 0; t < NTILE; t++) {
            const float* q = base + (size_t)t*NSH*3;
            hp += q[0]; pp += q[1]; mp += q[2];
        }
        const float bias = (SL - ssp) / Sm;
        const float num  = Shh - 2.f*hp + pp - 2.f*bias*(SL - mp) + bias*bias*Sm;
        mse = num / Sm;
    }
    if (tid < 64) smin[tid] = mse;
    __syncthreads();
    #pragma unroll
    for (int off = 32; off; off >>= 1) {
        if (tid < off) smin[tid] = fminf(smin[tid], smin[tid + off]);
        __syncthreads();
    }
    if (tid == 0) {
        g_bmin[b] = smin[0];
        __threadfence();
        is_last = (atomicAdd(&g_ctr, 1) == Bn - 1) ? 1 : 0;
    }
    __syncthreads();

    if (is_last) {
        __threadfence();
        if (tid < 64) smin[tid] = g_bmin[tid];
        __syncthreads();
        #pragma unroll
        for (int off = 32; off; off >>= 1) {
            if (tid < off) smin[tid] += smin[tid + off];
            __syncthreads();
        }
        if (tid == 0) {
            out[0] = smin[0] * (1.f / (float)Bn);
            g_ctr = 0;
        }
    }
}

extern "C" void kernel_launch(void* const* d_in, const int* in_sizes, int n_in,
                              void* d_out, int out_size)
{
    const float* sr = (const float*)d_in[0];
    const float* hr = (const float*)d_in[1];
    const float* mk = (const float*)d_in[2];
    (void)in_sizes; (void)n_in; (void)out_size;

    corr_kernel<<<dim3(GX, GY, Bn), NT>>>(sr, hr, mk);
    mse_kernel<<<Bn, NT>>>((float*)d_out);
}

// round 9
// speedup vs baseline: 1.8852x; 1.0774x over previous
#include <cuda_runtime.h>

#define Bn 64
#define H  384
#define HH (H*H)
#define BORDER 3
#define CROP 378
#define NSH 49

// corr tiling: 3 x 24 tiles exactly partition 384 x 384 (owned 128 x 16 each)
#define TX 128
#define TY 16
#define GX 3
#define GY 24
#define NTILE (GX*GY)   // 72
#define HALO_W 136      // need 134, pad to 136 (16B-safe rows)
#define HALO_H 22       // TY + 6
#define NT 224          // threads per corr block
#define NTM 288         // threads per mse block (9 warps)

// scratch (static device memory; zero-initialized; no allocations anywhere)
__device__ float g_part [Bn*NSH*3*NTILE];   // corr partials: [b][shift][comp][tile]
__device__ float g_rsum [Bn*H*3*3];         // per (b,y,bx): {Sm,SL,Shh} partial
__device__ float g_eL   [Bn*H*3*6];         // left edge cols 0..5 per field
__device__ float g_eR   [Bn*H*3*6];         // right edge cols 378..383 per field
__device__ float g_ppart[Bn*NTILE];         // per-tile sum of pred
__device__ float g_bmin [Bn];               // per-batch min cMSE
__device__ int   g_ctr;                     // last-block counter (returns to 0)

// ---------------------------------------------------------------------------
// corr_kernel: three 7x7 correlations Shp, Spp, Smp (tile partials) + fused
// box row-sum partials. 7 warps; warp w owns shift-row i = w.
// ---------------------------------------------------------------------------
__global__ __launch_bounds__(NT) void corr_kernel(
    const float* __restrict__ sr, const float* __restrict__ hr,
    const float* __restrict__ mk)
{
    __shared__ __align__(16) float s_m [HALO_H*HALO_W];
    __shared__ __align__(16) float s_mh[HALO_H*HALO_W];
    __shared__ __align__(16) float s_p [TY*TX];
    __shared__ __align__(16) float s_pp[TY*TX];
    __shared__ float s_red[8];

    const int batch = blockIdx.z;
    const int bxi = blockIdx.x, byi = blockIdx.y;
    const int x0 = bxi * TX;
    const int y0 = byi * TY;
    const float* mb = mk + (size_t)batch*HH;
    const float* hb = hr + (size_t)batch*HH;
    const float* sb = sr + (size_t)batch*HH;
    const int tid  = threadIdx.x;
    const int wid  = tid >> 5;
    const int lane = tid & 31;

    // ---- halo tiles of m and m*h via float4 (rows 22, 34 float4 cols) ----
    for (int idx = tid; idx < HALO_H*34; idx += NT) {
        const int r  = idx / 34, c4 = idx % 34;
        const int y  = y0 + r, x = x0 + c4*4;
        float4 m4 = make_float4(0.f,0.f,0.f,0.f);
        float4 h4 = make_float4(0.f,0.f,0.f,0.f);
        if (y < H && x + 3 < H) {
            m4 = *(const float4*)&mb[y*H + x];
            h4 = *(const float4*)&hb[y*H + x];
            if (c4 == 33) { m4.z = 0.f; m4.w = 0.f; }   // cols 134,135 are pad
        }
        float4 l4;
        l4.x = m4.x*h4.x; l4.y = m4.y*h4.y; l4.z = m4.z*h4.z; l4.w = m4.w*h4.w;
        *(float4*)&s_m [r*HALO_W + c4*4] = m4;
        *(float4*)&s_mh[r*HALO_W + c4*4] = l4;
    }
    __syncthreads();

    // ---- fused box partials from owned 16x128 region ----
    for (int r = wid; r < TY; r += 7) {
        const float4 m4 = *(const float4*)&s_m [r*HALO_W + lane*4];
        const float4 l4 = *(const float4*)&s_mh[r*HALO_W + lane*4];
        float sm = m4.x + m4.y + m4.z + m4.w;
        float sl = l4.x + l4.y + l4.z + l4.w;
        float sh = l4.x*l4.x + l4.y*l4.y + l4.z*l4.z + l4.w*l4.w;  // m*h^2 (m binary)
        #pragma unroll
        for (int off = 16; off; off >>= 1) {
            sm += __shfl_xor_sync(0xffffffffu, sm, off);
            sl += __shfl_xor_sync(0xffffffffu, sl, off);
            sh += __shfl_xor_sync(0xffffffffu, sh, off);
        }
        if (lane == 0) {
            float* q = g_rsum + (((size_t)batch*H + (y0+r))*3 + bxi)*3;
            q[0] = sm; q[1] = sl; q[2] = sh;
        }
    }
    if (bxi == 0 && tid < 96) {
        const int r = tid / 6, c = tid % 6;
        const float m = s_m[r*HALO_W + c], l = s_mh[r*HALO_W + c];
        float* q = g_eL + ((size_t)batch*H + (y0+r))*18;
        q[0*6+c] = m; q[1*6+c] = l; q[2*6+c] = l*l;
    }
    if (bxi == 2 && tid < 96) {
        const int r = tid / 6, c = tid % 6;
        const float m = s_m[r*HALO_W + 122 + c], l = s_mh[r*HALO_W + 122 + c];
        float* q = g_eR + ((size_t)batch*H + (y0+r))*18;
        q[0*6+c] = m; q[1*6+c] = l; q[2*6+c] = l*l;
    }

    // ---- pred tile from sr (global) * mask (smem); accumulate sum(pred) ----
    float tp = 0.f;
    for (int idx = tid; idx < TY*TX; idx += NT) {
        const int r = idx >> 7, c = idx & 127;
        const int y = y0 + r, x = x0 + c;   // pred (crop) coordinates
        float p = 0.f;
        if (y < CROP && x < CROP)
            p = sb[(y+BORDER)*H + (x+BORDER)] * s_m[(r+BORDER)*HALO_W + (c+BORDER)];
        s_p[idx] = p; s_pp[idx] = p*p;
        tp += p;
    }
    #pragma unroll
    for (int off = 16; off; off >>= 1)
        tp += __shfl_xor_sync(0xffffffffu, tp, off);
    if (lane == 0) s_red[wid] = tp;
    __syncthreads();
    if (tid == 0) {
        float s = 0.f;
        #pragma unroll
        for (int k = 0; k < 7; k++) s += s_red[k];
        g_ppart[(size_t)batch*NTILE + byi*GX + bxi] = s;
    }

    // ---- main correlation loop (R1-proven scalar core) ----
    const int cb = lane * 4;
    float a_hp[7], a_pp[7], a_mp[7];
    #pragma unroll
    for (int j = 0; j < 7; j++) { a_hp[j]=0.f; a_pp[j]=0.f; a_mp[j]=0.f; }

    for (int r = 0; r < TY; r++) {
        const float4 p4 = *(const float4*)&s_p [r*TX + cb];
        const float4 q4 = *(const float4*)&s_pp[r*TX + cb];
        const float pv[4] = {p4.x, p4.y, p4.z, p4.w};
        const float qv[4] = {q4.x, q4.y, q4.z, q4.w};

        const int hbase = (r + wid)*HALO_W + cb;
        float mw[10], hw[10];
        {
            float4 t; float2 u;
            t = *(const float4*)&s_m[hbase];    mw[0]=t.x; mw[1]=t.y; mw[2]=t.z; mw[3]=t.w;
            t = *(const float4*)&s_m[hbase+4];  mw[4]=t.x; mw[5]=t.y; mw[6]=t.z; mw[7]=t.w;
            u = *(const float2*)&s_m[hbase+8];  mw[8]=u.x; mw[9]=u.y;
            t = *(const float4*)&s_mh[hbase];   hw[0]=t.x; hw[1]=t.y; hw[2]=t.z; hw[3]=t.w;
            t = *(const float4*)&s_mh[hbase+4]; hw[4]=t.x; hw[5]=t.y; hw[6]=t.z; hw[7]=t.w;
            u = *(const float2*)&s_mh[hbase+8]; hw[8]=u.x; hw[9]=u.y;
        }
        #pragma unroll
        for (int j = 0; j < 7; j++) {
            #pragma unroll
            for (int k = 0; k < 4; k++) {
                a_hp[j] = fmaf(hw[j+k], pv[k], a_hp[j]);
                a_mp[j] = fmaf(mw[j+k], pv[k], a_mp[j]);
                a_pp[j] = fmaf(mw[j+k], qv[k], a_pp[j]);
            }
        }
    }

    #pragma unroll
    for (int j = 0; j < 7; j++) {
        #pragma unroll
        for (int off = 16; off; off >>= 1) {
            a_hp[j] += __shfl_xor_sync(0xffffffffu, a_hp[j], off);
            a_pp[j] += __shfl_xor_sync(0xffffffffu, a_pp[j], off);
            a_mp[j] += __shfl_xor_sync(0xffffffffu, a_mp[j], off);
        }
    }
    if (lane == 0) {
        const int tile = byi*GX + bxi;
        #pragma unroll
        for (int j = 0; j < 7; j++) {
            const size_t s = (size_t)batch*NSH + wid*7 + j;
            g_part[(s*3 + 0)*NTILE + tile] = a_hp[j];
            g_part[(s*3 + 1)*NTILE + tile] = a_pp[j];
            g_part[(s*3 + 2)*NTILE + tile] = a_mp[j];
        }
    }
}

// ---------------------------------------------------------------------------
// mse_kernel v2: coalesced column sums of row partials/edges, window algebra
// in smem, per-shift tile sums via contiguous warp loads; min over shifts;
// last block -> mean -> out. 288 threads (9 warps).
// ---------------------------------------------------------------------------
__global__ __launch_bounds__(NTM) void mse_kernel(float* __restrict__ out)
{
    const int b = blockIdx.x;
    const int tid  = threadIdx.x;
    const int w    = tid >> 5;
    const int lane = tid & 31;

    __shared__ float sA[32][9];
    __shared__ float sL[16][18];
    __shared__ float sR[16][18];
    __shared__ float Tq[9], GL[18], GR[18];
    __shared__ float eRaw[12][45];   // [r][0..8 rsum | 9..26 eL | 27..44 eR]
    __shared__ float e_w[12][3][7];
    __shared__ float ctot[3][7];
    __shared__ float ssp;
    __shared__ float s_mse[64];
    __shared__ int   is_last;

    // ---- coalesced column sums ----
    {   // g_rsum: 384 rows x 9; thread owns component tid%9, rows tid/9 + 32k
        const int c = tid % 9, g = tid / 9;   // g in 0..31
        float acc = 0.f;
        const float* base = g_rsum + (size_t)b*H*9;
        for (int y = g; y < H; y += 32) acc += base[y*9 + c];
        sA[g][c] = acc;
    }
    {   // g_eL / g_eR: 384 rows x 18
        const int c = tid % 18, g = tid / 18;  // g in 0..15
        float aL = 0.f, aR = 0.f;
        const float* bl = g_eL + (size_t)b*H*18;
        const float* br = g_eR + (size_t)b*H*18;
        for (int y = g; y < H; y += 16) { aL += bl[y*18 + c]; aR += br[y*18 + c]; }
        sL[g][c] = aL; sR[g][c] = aR;
    }
    // edge rows raw (12 rows x 45 values)
    for (int t = tid; t < 12*45; t += NTM) {
        const int r = t / 45, c = t % 45;
        const int y = (r < 6) ? r : (372 + r);
        float v;
        if (c < 9)       v = g_rsum[((size_t)b*H + y)*9 + c];
        else if (c < 27) v = g_eL [((size_t)b*H + y)*18 + (c-9)];
        else             v = g_eR [((size_t)b*H + y)*18 + (c-27)];
        eRaw[r][c] = v;
    }
    // pred total (warp 8)
    if (w == 8) {
        const float* q = g_ppart + (size_t)b*NTILE;
        float c = q[lane] + q[lane+32] + ((lane < 8) ? q[lane+64] : 0.f);
        #pragma unroll
        for (int off = 16; off; off >>= 1)
            c += __shfl_xor_sync(0xffffffffu, c, off);
        if (lane == 0) ssp = c;
    }
    __syncthreads();

    if (tid < 9)       { float s=0.f; for (int g=0; g<32; g++) s += sA[g][tid];    Tq[tid]   = s; }
    else if (tid < 27) { const int c=tid-9;  float s=0.f; for (int g=0; g<16; g++) s += sL[g][c]; GL[c] = s; }
    else if (tid < 45) { const int c=tid-27; float s=0.f; for (int g=0; g<16; g++) s += sR[g][c]; GR[c] = s; }
    __syncthreads();

    if (tid < 21) {
        const int f = tid / 7, j = tid % 7;
        float T = Tq[f] + Tq[3+f] + Tq[6+f];
        for (int k = 0; k < j; k++) T -= GL[f*6 + k];
        for (int k = j; k < 6; k++) T -= GR[f*6 + k];
        ctot[f][j] = T;
    }
    if (tid < 252) {
        const int r = tid / 21, rest = tid % 21;
        const int f = rest / 7, j = rest % 7;
        float T = eRaw[r][f] + eRaw[r][3+f] + eRaw[r][6+f];
        for (int k = 0; k < j; k++) T -= eRaw[r][9  + f*6 + k];
        for (int k = j; k < 6; k++) T -= eRaw[r][27 + f*6 + k];
        e_w[r][f][j] = T;
    }
    if (tid >= 252 && tid < 252+15) s_mse[NSH + (tid-252)] = 3.4e38f;  // pad 49..63
    __syncthreads();

    // ---- per-shift: warp w < 7 handles shifts w*7 .. w*7+6 ----
    if (w < 7) {
        #pragma unroll
        for (int q = 0; q < 7; q++) {
            const int s = w*7 + q;
            float comp[3];
            #pragma unroll
            for (int c = 0; c < 3; c++) {
                const float* base = g_part + (((size_t)b*NSH + s)*3 + c)*NTILE;
                float v = base[lane] + base[lane+32] + ((lane < 8) ? base[lane+64] : 0.f);
                #pragma unroll
                for (int off = 16; off; off >>= 1)
                    v += __shfl_xor_sync(0xffffffffu, v, off);
                comp[c] = v;
            }
            if (lane == 0) {
                const int i = s / 7, jc = s % 7;
                float Sm  = ctot[0][jc];
                float SL  = ctot[1][jc];
                float Shh = ctot[2][jc];
                for (int y = 0; y < i; y++) {
                    Sm -= e_w[y][0][jc]; SL -= e_w[y][1][jc]; Shh -= e_w[y][2][jc];
                }
                for (int t = i + 6; t < 12; t++) {
                    Sm -= e_w[t][0][jc]; SL -= e_w[t][1][jc]; Shh -= e_w[t][2][jc];
                }
                const float hp = comp[0], pp = comp[1], mp = comp[2];
                const float bias = (SL - ssp) / Sm;
                const float num  = Shh - 2.f*hp + pp - 2.f*bias*(SL - mp) + bias*bias*Sm;
                s_mse[s] = num / Sm;
            }
        }
    }
    __syncthreads();

    // min over 49 (padded to 64)
    #pragma unroll
    for (int off = 32; off; off >>= 1) {
        if (tid < off) s_mse[tid] = fminf(s_mse[tid], s_mse[tid + off]);
        __syncthreads();
    }
    if (tid == 0) {
        g_bmin[b] = s_mse[0];
        __threadfence();
        is_last = (atomicAdd(&g_ctr, 1) == Bn - 1) ? 1 : 0;
    }
    __syncthreads();

    if (is_last) {
        __threadfence();
        if (tid < 64) s_mse[tid] = g_bmin[tid];
        __syncthreads();
        #pragma unroll
        for (int off = 32; off; off >>= 1) {
            if (tid < off) s_mse[tid] += s_mse[tid + off];
            __syncthreads();
        }
        if (tid == 0) {
            out[0] = s_mse[0] * (1.f / (float)Bn);
            g_ctr = 0;
        }
    }
}

extern "C" void kernel_launch(void* const* d_in, const int* in_sizes, int n_in,
                              void* d_out, int out_size)
{
    const float* sr = (const float*)d_in[0];
    const float* hr = (const float*)d_in[1];
    const float* mk = (const float*)d_in[2];
    (void)in_sizes; (void)n_in; (void)out_size;

    corr_kernel<<<dim3(GX, GY, Bn), NT>>>(sr, hr, mk);
    mse_kernel<<<Bn, NTM>>>((float*)d_out);
}